// round 1
// baseline (speedup 1.0000x reference)
#include <cuda_runtime.h>

// ---------------- problem constants ----------------
#define Fn 16          // B*T frames
#define Cn 64          // channels
#define Hn 128
#define Wn 128
#define HWn (128*128)  // 16384
#define HOn 64
#define WOn 64
#define NEG 0.2f

// ---------------- device scratch (no allocations allowed) ----------------
__device__ float g_xf  [Fn*Cn*HWn];    // x transposed to frame-major
__device__ float g_bufA[Fn*Cn*HWn];    // r1, later k1
__device__ float g_bufB[Fn*Cn*HWn];    // shift-product, later k2
__device__ float g_x5  [Fn*Cn*HWn];    // x5 (residual sum)
__device__ float g_kf  [Fn*9*HOn*WOn]; // strided conv logits
__device__ float g_w1t [Cn*Cn*9];      // transposed weights [ic][j][oc]
__device__ float g_w2t [Cn*Cn*9];
__device__ float g_wk2t[Cn*Cn*9];
__device__ float g_wk1t[Cn*Cn];        // [c][o]
__device__ float g_wk3t[Cn*9*9];       // [(c*9+j)][k]

// ---------------- kernels ----------------

// (B,C,T,H,W) -> frame-major (B*T, C, H, W)
__global__ void k_transpose(const float* __restrict__ x) {
    int idx = blockIdx.x * 256 + threadIdx.x;      // exact coverage
    int c = (idx >> 14) & 63;
    int f = idx >> 20;
    int b = f >> 3, t = f & 7;
    g_xf[idx] = x[(((b * 64 + c) * 8 + t) << 14) + (idx & 16383)];
}

// transpose all weights for coalesced smem staging
__global__ void k_prep(const float* __restrict__ w1, const float* __restrict__ w2,
                       const float* __restrict__ wk2, const float* __restrict__ wk1,
                       const float* __restrict__ wk3) {
    int idx = blockIdx.x * 256 + threadIdx.x;      // grid covers 36864 exactly
    {
        int oc = idx / 576, ic = (idx / 9) % 64, j = idx % 9;
        int dst = (ic * 9 + j) * 64 + oc;
        g_w1t[dst]  = w1[idx];
        g_w2t[dst]  = w2[idx];
        g_wk2t[dst] = wk2[idx];
    }
    if (idx < 4096) { int o = idx >> 6, c = idx & 63; g_wk1t[c * 64 + o] = wk1[idx]; }
    if (idx < 5184) {
        int k = idx / 576, c = (idx / 9) % 64, j = idx % 9;
        g_wk3t[(c * 9 + j) * 9 + k] = wk3[idx];
    }
}

// direct 3x3 conv, 64->64, zero pad 1. Block: 8x32 pixel tile, all 64 oc.
template<bool LRELU, bool RESID>
__global__ void __launch_bounds__(256)
k_conv3x3(const float* __restrict__ in, const float* __restrict__ wt,
          const float* __restrict__ bias, const float* __restrict__ resid,
          float* __restrict__ out)
{
    const int f  = blockIdx.z;
    const int h0 = blockIdx.y * 8;
    const int w0 = blockIdx.x * 32;
    const int tid = threadIdx.x;
    const int tx = tid & 31, ty = tid >> 5;

    __shared__ float  s_in[4][10][34];
    __shared__ float4 s_w4[4 * 9 * 16];   // [icl][j][oc/4]

    float acc[64];
#pragma unroll
    for (int o = 0; o < 64; o++) acc[o] = 0.f;

    for (int ic0 = 0; ic0 < 64; ic0 += 4) {
        __syncthreads();
        // weights: contiguous 2304-float block (pre-transposed)
        const float* wsrc = wt + ic0 * 576;
        float* s_wf = (float*)s_w4;
        for (int p = tid; p < 2304; p += 256) s_wf[p] = wsrc[p];
        // input tile with halo
        for (int p = tid; p < 4 * 10 * 34; p += 256) {
            int icl = p / 340;
            int r   = (p % 340) / 34;
            int cc  = p % 34;
            int gh = h0 + r - 1, gw = w0 + cc - 1;
            float v = 0.f;
            if ((unsigned)gh < 128u && (unsigned)gw < 128u)
                v = in[(((f << 6) + ic0 + icl) << 14) + (gh << 7) + gw];
            s_in[icl][r][cc] = v;
        }
        __syncthreads();

        for (int icl = 0; icl < 4; ++icl) {
            float tap[9];
#pragma unroll
            for (int dy = 0; dy < 3; dy++)
#pragma unroll
                for (int dx = 0; dx < 3; dx++)
                    tap[dy * 3 + dx] = s_in[icl][ty + dy][tx + dx];
#pragma unroll
            for (int j = 0; j < 9; j++) {
                float tp = tap[j];
                const float4* wj = s_w4 + (icl * 9 + j) * 16;  // uniform addr -> broadcast
#pragma unroll
                for (int o4 = 0; o4 < 16; o4++) {
                    float4 w = wj[o4];
                    acc[4 * o4 + 0] += tp * w.x;
                    acc[4 * o4 + 1] += tp * w.y;
                    acc[4 * o4 + 2] += tp * w.z;
                    acc[4 * o4 + 3] += tp * w.w;
                }
            }
        }
    }
    const int pix = ((h0 + ty) << 7) + (w0 + tx);
#pragma unroll
    for (int o = 0; o < 64; o++) {
        float v = acc[o] + __ldg(&bias[o]);
        if (LRELU) v = v >= 0.f ? v : NEG * v;
        int oidx = (((f << 6) + o) << 14) + pix;
        if (RESID) v += resid[oidx];
        out[oidx] = v;
    }
}

// spatial shift (4-direction, groups of 16) multiplied elementwise by input
__global__ void k_shift(const float* __restrict__ in, float* __restrict__ out) {
    int idx = blockIdx.x * 256 + threadIdx.x;
    int w = idx & 127, h = (idx >> 7) & 127, c = (idx >> 14) & 63;
    int g = c >> 4;
    float a = in[idx], s;
    if      (g == 0) s = (w >= 4)   ? in[idx - 4]   : 0.f;  // shift right
    else if (g == 1) s = (w < 124)  ? in[idx + 4]   : 0.f;  // shift left
    else if (g == 2) s = (h >= 4)   ? in[idx - 512] : 0.f;  // shift down
    else             s = (h < 124)  ? in[idx + 512] : 0.f;  // shift up
    out[idx] = a * s;
}

// 1x1 conv (64x64 GEMM per pixel)
__global__ void __launch_bounds__(256)
k_conv1x1(const float* __restrict__ in, const float* __restrict__ wt,
          const float* __restrict__ bias, float* __restrict__ out)
{
    const int f = blockIdx.y;
    const int p = blockIdx.x * 256 + threadIdx.x;
    __shared__ float4 s_w4[1024];                  // [c][o/4]
    for (int q = threadIdx.x; q < 1024; q += 256) s_w4[q] = ((const float4*)wt)[q];
    __syncthreads();
    float acc[64];
#pragma unroll
    for (int o = 0; o < 64; o++) acc[o] = 0.f;
    const float* inp = in + (f << 20) + p;
    for (int c = 0; c < 64; c++) {
        float tp = inp[c << 14];
#pragma unroll
        for (int o4 = 0; o4 < 16; o4++) {
            float4 w = s_w4[(c << 4) + o4];
            acc[4 * o4 + 0] += tp * w.x;
            acc[4 * o4 + 1] += tp * w.y;
            acc[4 * o4 + 2] += tp * w.z;
            acc[4 * o4 + 3] += tp * w.w;
        }
    }
#pragma unroll
    for (int o = 0; o < 64; o++)
        out[(f << 20) + (o << 14) + p] = acc[o] + __ldg(&bias[o]);
}

// strided (s=2, pad=1) 3x3 conv, 64->9 channels, output 64x64
__global__ void __launch_bounds__(256)
k_convs2(const float* __restrict__ in, const float* __restrict__ wt,
         const float* __restrict__ bias, float* __restrict__ out)
{
    const int f  = blockIdx.y;
    const int tid = threadIdx.x;
    const int wo = tid & 63, ty = tid >> 6;
    const int ho = blockIdx.x * 4 + ty;
    __shared__ float s_w[5184];
    for (int p = tid; p < 5184; p += 256) s_w[p] = wt[p];
    __syncthreads();
    float acc[9];
#pragma unroll
    for (int k = 0; k < 9; k++) acc[k] = 0.f;
    for (int c = 0; c < 64; c++) {
        const float* bp = in + (((f << 6) + c) << 14);
        float tap[9];
#pragma unroll
        for (int dy = 0; dy < 3; dy++) {
            int hh = 2 * ho + dy - 1;
            bool hv = (unsigned)hh < 128u;
#pragma unroll
            for (int dx = 0; dx < 3; dx++) {
                int ww = 2 * wo + dx - 1;
                tap[dy * 3 + dx] = (hv && (unsigned)ww < 128u) ? __ldg(bp + (hh << 7) + ww) : 0.f;
            }
        }
#pragma unroll
        for (int j = 0; j < 9; j++) {
            float tp = tap[j];
            const float* wp = s_w + (c * 9 + j) * 9;
#pragma unroll
            for (int k = 0; k < 9; k++) acc[k] += tp * wp[k];
        }
    }
#pragma unroll
    for (int k = 0; k < 9; k++)
        out[((f * 9 + k) << 12) + (ho << 6) + wo] = acc[k] + __ldg(&bias[k]);
}

// softmax over 72 (t,ki,kj) logits + weighted gather of x5 patches (replicate pad)
__global__ void __launch_bounds__(256)
k_final(const float* __restrict__ x5, const float* __restrict__ kf,
        float* __restrict__ out)
{
    const int ho = blockIdx.x;
    const int b  = blockIdx.y;
    const int wo = threadIdx.x & 63;
    const int cg = threadIdx.x >> 6;   // 4 channel groups of 16

    float wgt[72];
    float mx = -1e30f;
#pragma unroll
    for (int t = 0; t < 8; t++)
#pragma unroll
        for (int kk = 0; kk < 9; kk++) {
            float v = kf[(((b * 8 + t) * 9 + kk) << 12) + (ho << 6) + wo];
            wgt[t * 9 + kk] = v;
            mx = fmaxf(mx, v);
        }
    float s = 0.f;
#pragma unroll
    for (int q = 0; q < 72; q++) { float e = __expf(wgt[q] - mx); wgt[q] = e; s += e; }
    float inv = 1.f / s;
#pragma unroll
    for (int q = 0; q < 72; q++) wgt[q] *= inv;

    for (int ci = 0; ci < 16; ++ci) {
        int c = cg * 16 + ci;
        float acc = 0.f;
#pragma unroll
        for (int t = 0; t < 8; t++) {
            const float* xb = x5 + (((b * 8 + t) * 64 + c) << 14);
#pragma unroll
            for (int i = 0; i < 3; i++) {
                int hh = 2 * ho + i - 1;
                hh = hh < 0 ? 0 : (hh > 127 ? 127 : hh);
                const float* row = xb + (hh << 7);
#pragma unroll
                for (int j = 0; j < 3; j++) {
                    int ww = 2 * wo + j - 1;
                    ww = ww < 0 ? 0 : ww;
                    acc += row[ww] * wgt[t * 9 + i * 3 + j];
                }
            }
        }
        out[((b * 64 + c) << 12) + (ho << 6) + wo] = acc;
    }
}

// ---------------- launch ----------------
extern "C" void kernel_launch(void* const* d_in, const int* in_sizes, int n_in,
                              void* d_out, int out_size)
{
    const float* x   = (const float*)d_in[0];
    const float* w1  = (const float*)d_in[1];
    const float* b1  = (const float*)d_in[2];
    const float* w2  = (const float*)d_in[3];
    const float* b2  = (const float*)d_in[4];
    const float* wk1 = (const float*)d_in[5];
    const float* bk1 = (const float*)d_in[6];
    const float* wk2 = (const float*)d_in[7];
    const float* bk2 = (const float*)d_in[8];
    const float* wk3 = (const float*)d_in[9];
    const float* bk3 = (const float*)d_in[10];
    float* out = (float*)d_out;

    float *xf, *bufA, *bufB, *x5, *kf, *w1t, *w2t, *wk2t, *wk1t, *wk3t;
    cudaGetSymbolAddress((void**)&xf,   g_xf);
    cudaGetSymbolAddress((void**)&bufA, g_bufA);
    cudaGetSymbolAddress((void**)&bufB, g_bufB);
    cudaGetSymbolAddress((void**)&x5,   g_x5);
    cudaGetSymbolAddress((void**)&kf,   g_kf);
    cudaGetSymbolAddress((void**)&w1t,  g_w1t);
    cudaGetSymbolAddress((void**)&w2t,  g_w2t);
    cudaGetSymbolAddress((void**)&wk2t, g_wk2t);
    cudaGetSymbolAddress((void**)&wk1t, g_wk1t);
    cudaGetSymbolAddress((void**)&wk3t, g_wk3t);

    k_transpose<<<65536, 256>>>(x);
    k_prep<<<144, 256>>>(w1, w2, wk2, wk1, wk3);

    dim3 cg(4, 16, 16);
    // conv1 + lrelu
    k_conv3x3<true , false><<<cg, 256>>>(xf, w1t, b1, nullptr, bufA);
    // spatial shift product
    k_shift<<<65536, 256>>>(bufA, bufB);
    // conv2 + residual -> x5
    k_conv3x3<false, true ><<<cg, 256>>>(bufB, w2t, b2, xf, x5);
    // 1x1 conv (wk1)
    k_conv1x1<<<dim3(64, 16), 256>>>(x5, wk1t, bk1, bufA);
    // conv wk2 + lrelu
    k_conv3x3<true , false><<<cg, 256>>>(bufA, wk2t, bk2, nullptr, bufB);
    // strided conv wk3 -> logits
    k_convs2<<<dim3(16, 16), 256>>>(bufB, wk3t, bk3, kf);
    // softmax + weighted gather
    k_final<<<dim3(64, 2), 256>>>(x5, kf, out);
}

// round 2
// speedup vs baseline: 1.0521x; 1.0521x over previous
#include <cuda_runtime.h>

// ---------------- problem constants ----------------
#define Fn 16          // B*T frames
#define Cn 64          // channels
#define Hn 128
#define Wn 128
#define HWn (128*128)  // 16384
#define HOn 64
#define WOn 64
#define NEG 0.2f

// packed fp32x2 FMA (Blackwell; ptxas never emits it, PTX-only)
#define FMA_F32X2(d, a, b, c) \
    asm("fma.rn.f32x2 %0, %1, %2, %3;" : "=l"(d) : "l"(a), "l"(b), "l"(c))
#define PACK_DUP_F32X2(d, s) \
    asm("mov.b64 %0, {%1, %1};" : "=l"(d) : "r"(__float_as_uint(s)))

// ---------------- device scratch (no allocations allowed) ----------------
__device__ float g_xf  [Fn*Cn*HWn];    // x transposed to frame-major
__device__ float g_bufA[Fn*Cn*HWn];    // r1, later k1
__device__ float g_bufB[Fn*Cn*HWn];    // shift-product, later k2
__device__ float g_x5  [Fn*Cn*HWn];    // x5 (residual sum)
__device__ float g_kf  [Fn*9*HOn*WOn]; // strided conv logits
__device__ float g_w1t [Cn*Cn*9];      // transposed weights [ic][j][oc]
__device__ float g_w2t [Cn*Cn*9];
__device__ float g_wk2t[Cn*Cn*9];
__device__ float g_wk1t[Cn*Cn];        // [c][o]
__device__ float g_wk3t[Cn*9*9];       // [(c*9+j)][k]

// ---------------- kernels ----------------

// (B,C,T,H,W) -> frame-major (B*T, C, H, W)
__global__ void k_transpose(const float* __restrict__ x) {
    int idx = blockIdx.x * 256 + threadIdx.x;      // exact coverage
    int c = (idx >> 14) & 63;
    int f = idx >> 20;
    int b = f >> 3, t = f & 7;
    g_xf[idx] = x[(((b * 64 + c) * 8 + t) << 14) + (idx & 16383)];
}

// transpose all weights for coalesced smem staging
__global__ void k_prep(const float* __restrict__ w1, const float* __restrict__ w2,
                       const float* __restrict__ wk2, const float* __restrict__ wk1,
                       const float* __restrict__ wk3) {
    int idx = blockIdx.x * 256 + threadIdx.x;      // grid covers 36864 exactly
    {
        int oc = idx / 576, ic = (idx / 9) % 64, j = idx % 9;
        int dst = (ic * 9 + j) * 64 + oc;
        g_w1t[dst]  = w1[idx];
        g_w2t[dst]  = w2[idx];
        g_wk2t[dst] = wk2[idx];
    }
    if (idx < 4096) { int o = idx >> 6, c = idx & 63; g_wk1t[c * 64 + o] = wk1[idx]; }
    if (idx < 5184) {
        int k = idx / 576, c = (idx / 9) % 64, j = idx % 9;
        g_wk3t[(c * 9 + j) * 9 + k] = wk3[idx];
    }
}

// direct 3x3 conv, 64->64, zero pad 1. Block: 8x32 pixel tile, all 64 oc.
// Accumulators packed as 32 x f32x2 (pairs of adjacent output channels).
template<bool LRELU, bool RESID>
__global__ void __launch_bounds__(256)
k_conv3x3(const float* __restrict__ in, const float* __restrict__ wt,
          const float* __restrict__ bias, const float* __restrict__ resid,
          float* __restrict__ out)
{
    const int f  = blockIdx.z;
    const int h0 = blockIdx.y * 8;
    const int w0 = blockIdx.x * 32;
    const int tid = threadIdx.x;
    const int tx = tid & 31, ty = tid >> 5;

    __shared__ float  s_in[4][10][34];
    __shared__ float4 s_w4[4 * 9 * 16];   // [icl][j][oc/4]

    unsigned long long acc2[32];
#pragma unroll
    for (int q = 0; q < 32; q++) acc2[q] = 0ULL;

    for (int ic0 = 0; ic0 < 64; ic0 += 4) {
        __syncthreads();
        // weights: contiguous 2304-float block (pre-transposed)
        const float* wsrc = wt + ic0 * 576;
        float* s_wf = (float*)s_w4;
        for (int p = tid; p < 2304; p += 256) s_wf[p] = wsrc[p];
        // input tile with halo
        for (int p = tid; p < 4 * 10 * 34; p += 256) {
            int icl = p / 340;
            int r   = (p % 340) / 34;
            int cc  = p % 34;
            int gh = h0 + r - 1, gw = w0 + cc - 1;
            float v = 0.f;
            if ((unsigned)gh < 128u && (unsigned)gw < 128u)
                v = in[(((f << 6) + ic0 + icl) << 14) + (gh << 7) + gw];
            s_in[icl][r][cc] = v;
        }
        __syncthreads();

#pragma unroll
        for (int icl = 0; icl < 4; ++icl) {
            unsigned long long tap2[9];
#pragma unroll
            for (int dy = 0; dy < 3; dy++)
#pragma unroll
                for (int dx = 0; dx < 3; dx++) {
                    float t = s_in[icl][ty + dy][tx + dx];
                    PACK_DUP_F32X2(tap2[dy * 3 + dx], t);
                }
#pragma unroll
            for (int j = 0; j < 9; j++) {
                unsigned long long tp2 = tap2[j];
                const ulonglong2* wj = (const ulonglong2*)(s_w4 + (icl * 9 + j) * 16);
#pragma unroll
                for (int o4 = 0; o4 < 16; o4++) {
                    ulonglong2 w = wj[o4];        // uniform addr -> LDS.128 broadcast
                    FMA_F32X2(acc2[2 * o4 + 0], tp2, w.x, acc2[2 * o4 + 0]);
                    FMA_F32X2(acc2[2 * o4 + 1], tp2, w.y, acc2[2 * o4 + 1]);
                }
            }
        }
    }
    const int pix = ((h0 + ty) << 7) + (w0 + tx);
#pragma unroll
    for (int q = 0; q < 32; q++) {
        unsigned int ulo, uhi;
        asm("mov.b64 {%0, %1}, %2;" : "=r"(ulo), "=r"(uhi) : "l"(acc2[q]));
        float vlo = __uint_as_float(ulo) + __ldg(&bias[2 * q]);
        float vhi = __uint_as_float(uhi) + __ldg(&bias[2 * q + 1]);
        if (LRELU) {
            vlo = vlo >= 0.f ? vlo : NEG * vlo;
            vhi = vhi >= 0.f ? vhi : NEG * vhi;
        }
        int olo = (((f << 6) + 2 * q) << 14) + pix;
        if (RESID) { vlo += resid[olo]; vhi += resid[olo + HWn]; }
        out[olo] = vlo;
        out[olo + HWn] = vhi;
    }
}

// spatial shift (4-direction, groups of 16) multiplied elementwise by input
__global__ void k_shift(const float* __restrict__ in, float* __restrict__ out) {
    int idx = blockIdx.x * 256 + threadIdx.x;
    int w = idx & 127, h = (idx >> 7) & 127, c = (idx >> 14) & 63;
    int g = c >> 4;
    float a = in[idx], s;
    if      (g == 0) s = (w >= 4)   ? in[idx - 4]   : 0.f;  // shift right
    else if (g == 1) s = (w < 124)  ? in[idx + 4]   : 0.f;  // shift left
    else if (g == 2) s = (h >= 4)   ? in[idx - 512] : 0.f;  // shift down
    else             s = (h < 124)  ? in[idx + 512] : 0.f;  // shift up
    out[idx] = a * s;
}

// 1x1 conv (64x64 GEMM per pixel), f32x2 packed
__global__ void __launch_bounds__(256)
k_conv1x1(const float* __restrict__ in, const float* __restrict__ wt,
          const float* __restrict__ bias, float* __restrict__ out)
{
    const int f = blockIdx.y;
    const int p = blockIdx.x * 256 + threadIdx.x;
    __shared__ float4 s_w4[1024];                  // [c][o/4]
    for (int q = threadIdx.x; q < 1024; q += 256) s_w4[q] = ((const float4*)wt)[q];
    __syncthreads();
    unsigned long long acc2[32];
#pragma unroll
    for (int q = 0; q < 32; q++) acc2[q] = 0ULL;
    const float* inp = in + (f << 20) + p;
#pragma unroll 4
    for (int c = 0; c < 64; c++) {
        unsigned long long tp2;
        PACK_DUP_F32X2(tp2, inp[c << 14]);
        const ulonglong2* wj = (const ulonglong2*)(s_w4 + (c << 4));
#pragma unroll
        for (int o4 = 0; o4 < 16; o4++) {
            ulonglong2 w = wj[o4];
            FMA_F32X2(acc2[2 * o4 + 0], tp2, w.x, acc2[2 * o4 + 0]);
            FMA_F32X2(acc2[2 * o4 + 1], tp2, w.y, acc2[2 * o4 + 1]);
        }
    }
#pragma unroll
    for (int q = 0; q < 32; q++) {
        unsigned int ulo, uhi;
        asm("mov.b64 {%0, %1}, %2;" : "=r"(ulo), "=r"(uhi) : "l"(acc2[q]));
        out[(f << 20) + ((2 * q) << 14) + p]     = __uint_as_float(ulo) + __ldg(&bias[2 * q]);
        out[(f << 20) + ((2 * q + 1) << 14) + p] = __uint_as_float(uhi) + __ldg(&bias[2 * q + 1]);
    }
}

// strided (s=2, pad=1) 3x3 conv, 64->9 channels, output 64x64
__global__ void __launch_bounds__(256)
k_convs2(const float* __restrict__ in, const float* __restrict__ wt,
         const float* __restrict__ bias, float* __restrict__ out)
{
    const int f  = blockIdx.y;
    const int tid = threadIdx.x;
    const int wo = tid & 63, ty = tid >> 6;
    const int ho = blockIdx.x * 4 + ty;
    __shared__ float s_w[5184];
    for (int p = tid; p < 5184; p += 256) s_w[p] = wt[p];
    __syncthreads();
    float acc[9];
#pragma unroll
    for (int k = 0; k < 9; k++) acc[k] = 0.f;
    for (int c = 0; c < 64; c++) {
        const float* bp = in + (((f << 6) + c) << 14);
        float tap[9];
#pragma unroll
        for (int dy = 0; dy < 3; dy++) {
            int hh = 2 * ho + dy - 1;
            bool hv = (unsigned)hh < 128u;
#pragma unroll
            for (int dx = 0; dx < 3; dx++) {
                int ww = 2 * wo + dx - 1;
                tap[dy * 3 + dx] = (hv && (unsigned)ww < 128u) ? __ldg(bp + (hh << 7) + ww) : 0.f;
            }
        }
#pragma unroll
        for (int j = 0; j < 9; j++) {
            float tp = tap[j];
            const float* wp = s_w + (c * 9 + j) * 9;
#pragma unroll
            for (int k = 0; k < 9; k++) acc[k] += tp * wp[k];
        }
    }
#pragma unroll
    for (int k = 0; k < 9; k++)
        out[((f * 9 + k) << 12) + (ho << 6) + wo] = acc[k] + __ldg(&bias[k]);
}

// softmax over 72 (t,ki,kj) logits + weighted gather of x5 patches (replicate pad)
__global__ void __launch_bounds__(256)
k_final(const float* __restrict__ x5, const float* __restrict__ kf,
        float* __restrict__ out)
{
    const int ho = blockIdx.x;
    const int b  = blockIdx.y;
    const int wo = threadIdx.x & 63;
    const int cg = threadIdx.x >> 6;   // 4 channel groups of 16

    float wgt[72];
    float mx = -1e30f;
#pragma unroll
    for (int t = 0; t < 8; t++)
#pragma unroll
        for (int kk = 0; kk < 9; kk++) {
            float v = kf[(((b * 8 + t) * 9 + kk) << 12) + (ho << 6) + wo];
            wgt[t * 9 + kk] = v;
            mx = fmaxf(mx, v);
        }
    float s = 0.f;
#pragma unroll
    for (int q = 0; q < 72; q++) { float e = __expf(wgt[q] - mx); wgt[q] = e; s += e; }
    float inv = 1.f / s;
#pragma unroll
    for (int q = 0; q < 72; q++) wgt[q] *= inv;

    for (int ci = 0; ci < 16; ++ci) {
        int c = cg * 16 + ci;
        float acc = 0.f;
#pragma unroll
        for (int t = 0; t < 8; t++) {
            const float* xb = x5 + (((b * 8 + t) * 64 + c) << 14);
#pragma unroll
            for (int i = 0; i < 3; i++) {
                int hh = 2 * ho + i - 1;
                hh = hh < 0 ? 0 : (hh > 127 ? 127 : hh);
                const float* row = xb + (hh << 7);
#pragma unroll
                for (int j = 0; j < 3; j++) {
                    int ww = 2 * wo + j - 1;
                    ww = ww < 0 ? 0 : ww;
                    acc += row[ww] * wgt[t * 9 + i * 3 + j];
                }
            }
        }
        out[((b * 64 + c) << 12) + (ho << 6) + wo] = acc;
    }
}

// ---------------- launch ----------------
extern "C" void kernel_launch(void* const* d_in, const int* in_sizes, int n_in,
                              void* d_out, int out_size)
{
    const float* x   = (const float*)d_in[0];
    const float* w1  = (const float*)d_in[1];
    const float* b1  = (const float*)d_in[2];
    const float* w2  = (const float*)d_in[3];
    const float* b2  = (const float*)d_in[4];
    const float* wk1 = (const float*)d_in[5];
    const float* bk1 = (const float*)d_in[6];
    const float* wk2 = (const float*)d_in[7];
    const float* bk2 = (const float*)d_in[8];
    const float* wk3 = (const float*)d_in[9];
    const float* bk3 = (const float*)d_in[10];
    float* out = (float*)d_out;

    float *xf, *bufA, *bufB, *x5, *kf, *w1t, *w2t, *wk2t, *wk1t, *wk3t;
    cudaGetSymbolAddress((void**)&xf,   g_xf);
    cudaGetSymbolAddress((void**)&bufA, g_bufA);
    cudaGetSymbolAddress((void**)&bufB, g_bufB);
    cudaGetSymbolAddress((void**)&x5,   g_x5);
    cudaGetSymbolAddress((void**)&kf,   g_kf);
    cudaGetSymbolAddress((void**)&w1t,  g_w1t);
    cudaGetSymbolAddress((void**)&w2t,  g_w2t);
    cudaGetSymbolAddress((void**)&wk2t, g_wk2t);
    cudaGetSymbolAddress((void**)&wk1t, g_wk1t);
    cudaGetSymbolAddress((void**)&wk3t, g_wk3t);

    k_transpose<<<65536, 256>>>(x);
    k_prep<<<144, 256>>>(w1, w2, wk2, wk1, wk3);

    dim3 cg(4, 16, 16);
    // conv1 + lrelu
    k_conv3x3<true , false><<<cg, 256>>>(xf, w1t, b1, nullptr, bufA);
    // spatial shift product
    k_shift<<<65536, 256>>>(bufA, bufB);
    // conv2 + residual -> x5
    k_conv3x3<false, true ><<<cg, 256>>>(bufB, w2t, b2, xf, x5);
    // 1x1 conv (wk1)
    k_conv1x1<<<dim3(64, 16), 256>>>(x5, wk1t, bk1, bufA);
    // conv wk2 + lrelu
    k_conv3x3<true , false><<<cg, 256>>>(bufA, wk2t, bk2, nullptr, bufB);
    // strided conv wk3 -> logits
    k_convs2<<<dim3(16, 16), 256>>>(bufB, wk3t, bk3, kf);
    // softmax + weighted gather
    k_final<<<dim3(64, 2), 256>>>(x5, kf, out);
}